// round 15
// baseline (speedup 1.0000x reference)
#include <cuda_runtime.h>
#include <cuda_fp16.h>
#include <math.h>
#include <stdint.h>

#define B_   8
#define L_   8192
#define D_   512
#define H_   8
#define D3_  1536
#define M_   (B_ * L_)
#define EPS_ 1e-6f
#define NSC  16
#define SCHUNK (L_ / NSC)

// ---------------------------------------------------------------------------
// Scratch
// ---------------------------------------------------------------------------
__device__ __half g_A1 [(size_t)M_ * D3_];
__device__ __half g_W1 [(size_t)D3_ * D3_];
__device__ __half g_QKV[(size_t)M_ * D3_];
__device__ __half g_A2 [(size_t)M_ * D_];
__device__ __half g_W2 [(size_t)D_ * D_];
__device__ float g_KVP[NSC * 64 * 64 * 64];
__device__ float g_KSP[NSC * 64 * 64];
__device__ __half g_Battn[(size_t)64 * 136 * 64];

// ---------------------------------------------------------------------------
// PTX helpers
// ---------------------------------------------------------------------------
__device__ __forceinline__ void cp16(uint32_t dst, const void* src) {
    asm volatile("cp.async.cg.shared.global [%0], [%1], 16;" :: "r"(dst), "l"(src) : "memory");
}
__device__ __forceinline__ void cp_commit() {
    asm volatile("cp.async.commit_group;" ::: "memory");
}
template <int N>
__device__ __forceinline__ void cp_wait() {
    asm volatile("cp.async.wait_group %0;" :: "n"(N) : "memory");
}
__device__ __forceinline__ void ldsm4(uint32_t& r0, uint32_t& r1, uint32_t& r2, uint32_t& r3,
                                      uint32_t addr) {
    asm volatile("ldmatrix.sync.aligned.m8n8.x4.shared.b16 {%0,%1,%2,%3}, [%4];"
                 : "=r"(r0), "=r"(r1), "=r"(r2), "=r"(r3) : "r"(addr));
}
__device__ __forceinline__ void ldsm4t(uint32_t& r0, uint32_t& r1, uint32_t& r2, uint32_t& r3,
                                       uint32_t addr) {
    asm volatile("ldmatrix.sync.aligned.m8n8.x4.trans.shared.b16 {%0,%1,%2,%3}, [%4];"
                 : "=r"(r0), "=r"(r1), "=r"(r2), "=r"(r3) : "r"(addr));
}
__device__ __forceinline__ void mma16816(float* d, const uint32_t* a, uint32_t b0, uint32_t b1) {
    asm("mma.sync.aligned.m16n8k16.row.col.f32.f16.f16.f32 "
        "{%0,%1,%2,%3}, {%4,%5,%6,%7}, {%8,%9}, {%0,%1,%2,%3};"
        : "+f"(d[0]), "+f"(d[1]), "+f"(d[2]), "+f"(d[3])
        : "r"(a[0]), "r"(a[1]), "r"(a[2]), "r"(a[3]), "r"(b0), "r"(b1));
}
__device__ __forceinline__ float elu1(float x) {
    return x > 0.0f ? x + 1.0f : expf(x);
}

// ---------------------------------------------------------------------------
// GEMM1: CTA 128x128, BK=64, 3 stages, 8 warps (4m x 2n), warp 32x64.
// Identical per-warp inner step to R13; only barrier frequency halved.
// ---------------------------------------------------------------------------
#define B64_ROWB  144u
#define B64_TILE  (128u * B64_ROWB)     // 18432
#define B64_STG   (2u * B64_TILE)       // 36864
#define B64_SMEM  (3u * B64_STG)        // 110592

__global__ void __launch_bounds__(256, 2)
gemm1_bk64(const __half* __restrict__ A, const __half* __restrict__ Bw,
           __half* __restrict__ Ch)
{
    extern __shared__ char smem[];
    const uint32_t sb = (uint32_t)__cvta_generic_to_shared(smem);
    const int tid = threadIdx.x;
    const int w = tid >> 5, lane = tid & 31;
    const int mt = blockIdx.x / 12, nt = blockIdx.x % 12;
    const int wm = w & 3, wn = w >> 2;
    const uint32_t stag = (uint32_t)(w & 1) * 32;

    const __half* Ab = A  + (size_t)(mt * 128) * 1536;
    const __half* Bb = Bw + (size_t)(nt * 128) * 1536;

    // per stage: 128 rows x 8 chunks x 2 tiles = 2048 chunks, 8 per thread
    const int cr = tid >> 1, cc = (tid & 1) * 4;

    const uint32_t aoff = (uint32_t)(wm * 32 + (lane & 15)) * B64_ROWB + (uint32_t)(lane >> 4) * 16;
    const uint32_t boff = B64_TILE +
        (uint32_t)(wn * 64 + ((lane >> 4) << 3) + (lane & 7)) * B64_ROWB +
        (uint32_t)((lane >> 3) & 1) * 16;

    float acc[2][8][4];
    #pragma unroll
    for (int i = 0; i < 2; i++)
        #pragma unroll
        for (int j = 0; j < 8; j++)
            #pragma unroll
            for (int q = 0; q < 4; q++) acc[i][j][q] = 0.0f;

    auto load_stage = [&](int kt) {
        uint32_t base = sb + (uint32_t)(kt % 3) * B64_STG;
        int k0 = kt * 64;
        const __half* pa = Ab + (size_t)cr * 1536 + k0;
        const __half* pb = Bb + (size_t)cr * 1536 + k0;
        #pragma unroll
        for (int j = 0; j < 4; j++) {
            cp16(base + cr * B64_ROWB + (cc + j) * 16,            pa + (cc + j) * 8);
            cp16(base + B64_TILE + cr * B64_ROWB + (cc + j) * 16, pb + (cc + j) * 8);
        }
        cp_commit();
    };

    load_stage(0);
    load_stage(1);

    for (int kt = 0; kt < 24; kt++) {
        cp_wait<1>();
        __syncthreads();
        if (kt + 2 < 24) load_stage(kt + 2);
        else cp_commit();

        uint32_t base = sb + (uint32_t)(kt % 3) * B64_STG;
        #pragma unroll
        for (int s = 0; s < 4; s++) {
            uint32_t so = ((uint32_t)s * 32) ^ stag;
            uint32_t a[2][4], b[4][4];
            ldsm4(a[0][0], a[0][1], a[0][2], a[0][3], base + aoff + so);
            ldsm4(a[1][0], a[1][1], a[1][2], a[1][3], base + aoff + 16 * B64_ROWB + so);
            #pragma unroll
            for (int nb = 0; nb < 4; nb++)
                ldsm4(b[nb][0], b[nb][1], b[nb][2], b[nb][3],
                      base + boff + (uint32_t)nb * 16 * B64_ROWB + so);
            #pragma unroll
            for (int mi = 0; mi < 2; mi++)
                #pragma unroll
                for (int ni = 0; ni < 8; ni++)
                    mma16816(acc[mi][ni], a[mi],
                             b[ni >> 1][(ni & 1) * 2], b[ni >> 1][(ni & 1) * 2 + 1]);
        }
    }

    const int mrow = mt * 128 + wm * 32 + (lane >> 2);
    const int ncol = nt * 128 + wn * 64 + (lane & 3) * 2;
    #pragma unroll
    for (int mi = 0; mi < 2; mi++) {
        #pragma unroll
        for (int ni = 0; ni < 8; ni++) {
            int col = ncol + ni * 8;
            float x0 = acc[mi][ni][0], x1 = acc[mi][ni][1];
            float x2 = acc[mi][ni][2], x3 = acc[mi][ni][3];
            if (col < 1024)     { x0 = elu1(x0); x2 = elu1(x2); }
            if (col + 1 < 1024) { x1 = elu1(x1); x3 = elu1(x3); }
            int row = mrow + mi * 16;
            __half2* p0 = reinterpret_cast<__half2*>(Ch + (size_t)row * 1536 + col);
            __half2* p1 = reinterpret_cast<__half2*>(Ch + (size_t)(row + 8) * 1536 + col);
            *p0 = __floats2half2_rn(x0, x1);
            *p1 = __floats2half2_rn(x2, x3);
        }
    }
}

// ---------------------------------------------------------------------------
// GEMM2 (R13 frozen): out = A2 @ W2^T + bias (fp32)
// ---------------------------------------------------------------------------
#define STAGES 4
#define ROWB   80u
#define TILEB  (128u * ROWB)
#define STGB   (2u * TILEB)
#define GSMEM  (STAGES * STGB)

__global__ void __launch_bounds__(256, 2)
gemm_h16(const __half* __restrict__ A, const __half* __restrict__ Bw,
         float* __restrict__ C, const float* __restrict__ bias,
         int K, int NT, int Nout)
{
    extern __shared__ char smem[];
    const uint32_t sb = (uint32_t)__cvta_generic_to_shared(smem);
    const int tid = threadIdx.x;
    const int w = tid >> 5, lane = tid & 31;
    const int mt = blockIdx.x / NT, nt = blockIdx.x % NT;
    const int wm = w & 3, wn = w >> 2;
    const int ktiles = K >> 5;
    const uint32_t stag = (uint32_t)(w & 1) * 32;

    const __half* Ab = A  + (size_t)(mt * 128) * K;
    const __half* Bb = Bw + (size_t)(nt * 128) * K;

    const int r0c = tid >> 2,         c0c = tid & 3;
    const int r1c = (tid + 256) >> 2, c1c = c0c;

    const uint32_t aoff = (uint32_t)(wm * 32 + (lane & 15)) * ROWB + (uint32_t)(lane >> 4) * 16;
    const uint32_t boff = TILEB +
        (uint32_t)(wn * 64 + ((lane >> 4) << 3) + (lane & 7)) * ROWB +
        (uint32_t)((lane >> 3) & 1) * 16;

    float acc[2][8][4];
    #pragma unroll
    for (int i = 0; i < 2; i++)
        #pragma unroll
        for (int j = 0; j < 8; j++)
            #pragma unroll
            for (int q = 0; q < 4; q++) acc[i][j][q] = 0.0f;

    auto load_stage = [&](int kt) {
        uint32_t base = sb + (uint32_t)(kt & (STAGES - 1)) * STGB;
        int k0 = kt * 32;
        cp16(base + r0c * ROWB + c0c * 16,         Ab + (size_t)r0c * K + k0 + c0c * 8);
        cp16(base + r1c * ROWB + c1c * 16,         Ab + (size_t)r1c * K + k0 + c1c * 8);
        cp16(base + TILEB + r0c * ROWB + c0c * 16, Bb + (size_t)r0c * K + k0 + c0c * 8);
        cp16(base + TILEB + r1c * ROWB + c1c * 16, Bb + (size_t)r1c * K + k0 + c1c * 8);
        cp_commit();
    };

    load_stage(0);
    load_stage(1);
    load_stage(2);

    for (int kt = 0; kt < ktiles; kt++) {
        cp_wait<STAGES - 2>();
        __syncthreads();
        if (kt + STAGES - 1 < ktiles) load_stage(kt + STAGES - 1);
        else cp_commit();

        uint32_t base = sb + (uint32_t)(kt & (STAGES - 1)) * STGB;
        #pragma unroll
        for (int s = 0; s < 2; s++) {
            uint32_t so = ((uint32_t)s * 32) ^ stag;
            uint32_t a[2][4], b[4][4];
            ldsm4(a[0][0], a[0][1], a[0][2], a[0][3], base + aoff + so);
            ldsm4(a[1][0], a[1][1], a[1][2], a[1][3], base + aoff + 16 * ROWB + so);
            #pragma unroll
            for (int nb = 0; nb < 4; nb++)
                ldsm4(b[nb][0], b[nb][1], b[nb][2], b[nb][3],
                      base + boff + (uint32_t)nb * 16 * ROWB + so);
            #pragma unroll
            for (int mi = 0; mi < 2; mi++)
                #pragma unroll
                for (int ni = 0; ni < 8; ni++)
                    mma16816(acc[mi][ni], a[mi],
                             b[ni >> 1][(ni & 1) * 2], b[ni >> 1][(ni & 1) * 2 + 1]);
        }
    }

    const int mrow = mt * 128 + wm * 32 + (lane >> 2);
    const int ncol = nt * 128 + wn * 64 + (lane & 3) * 2;
    #pragma unroll
    for (int mi = 0; mi < 2; mi++) {
        #pragma unroll
        for (int ni = 0; ni < 8; ni++) {
            int col = ncol + ni * 8;
            float bv0 = bias[col], bv1 = bias[col + 1];
            int row = mrow + mi * 16;
            float2* p0 = reinterpret_cast<float2*>(C + (size_t)row * Nout + col);
            float2* p1 = reinterpret_cast<float2*>(C + (size_t)(row + 8) * Nout + col);
            *p0 = make_float2(acc[mi][ni][0] + bv0, acc[mi][ni][1] + bv1);
            *p1 = make_float2(acc[mi][ni][2] + bv0, acc[mi][ni][3] + bv1);
        }
    }
}

// ---------------------------------------------------------------------------
// Conversions fp32 -> fp16
// ---------------------------------------------------------------------------
__device__ __forceinline__ uint2 pack4h(float4 s) {
    __half2 h0 = __floats2half2_rn(s.x, s.y);
    __half2 h1 = __floats2half2_rn(s.z, s.w);
    uint2 r;
    r.x = *reinterpret_cast<uint32_t*>(&h0);
    r.y = *reinterpret_cast<uint32_t*>(&h1);
    return r;
}

__global__ void conv1_k(const float4* __restrict__ q, const float4* __restrict__ k,
                        const float4* __restrict__ v) {
    int i = blockIdx.x * 256 + threadIdx.x;
    int seg = i >> 23;
    int r   = i & ((1 << 23) - 1);
    int n   = r >> 7;
    int c4  = r & 127;
    const float4* src = (seg == 0) ? q : (seg == 1) ? k : v;
    float4 s = src[r];
    uint2* dst = reinterpret_cast<uint2*>(g_A1) + (size_t)n * 384 + seg * 128 + c4;
    *dst = pack4h(s);
}

__global__ void convw_k(const float* __restrict__ W, __half* __restrict__ Wd) {
    int i = blockIdx.x * 256 + threadIdx.x;
    float4 s = reinterpret_cast<const float4*>(W)[i];
    *reinterpret_cast<uint2*>(Wd + (size_t)i * 4) = pack4h(s);
}

// ---------------------------------------------------------------------------
// kv state via HMMA (R12 proven)
// ---------------------------------------------------------------------------
#define KV_VROWB 176u
#define KV_KROWB 144u
#define KV_VSZ   (32u * KV_VROWB)
#define KV_STG   (KV_VSZ + 32u * KV_KROWB)

__global__ void __launch_bounds__(256)
kv_mma(const __half* __restrict__ QKV) {
    __shared__ __align__(16) char smem[2 * KV_STG];
    const uint32_t sb = (uint32_t)__cvta_generic_to_shared(smem);
    const int bh = blockIdx.x, sc = blockIdx.y;
    const int b = bh >> 3, h = bh & 7;
    const int tid = threadIdx.x;
    const int w = tid >> 5, lane = tid & 31;

    for (int i = tid; i < 1024; i += 256) {
        int st = i >> 9, r = (i >> 4) & 31, c = i & 15;
        *reinterpret_cast<__half*>(smem + st * KV_STG + r * KV_VROWB + (64 + c) * 2) =
            __float2half(c == 0 ? 1.0f : 0.0f);
    }
    __syncthreads();

    const size_t rowg0 = (size_t)b * 8192 + (size_t)sc * SCHUNK;

    auto load_chunk = [&](int ch) {
        uint32_t base = sb + (uint32_t)(ch & 1) * KV_STG;
        #pragma unroll
        for (int o = tid; o < 512; o += 256) {
            int r = o >> 4, c = o & 15;
            size_t grow = (rowg0 + ch * 32 + r) * (size_t)D3_;
            if (c < 8)
                cp16(base + r * KV_VROWB + c * 16,
                     QKV + grow + 1024 + h * 64 + c * 8);
            else
                cp16(base + KV_VSZ + r * KV_KROWB + (c - 8) * 16,
                     QKV + grow + 512 + h * 64 + (c - 8) * 8);
        }
        cp_commit();
    };

    float acc[8][4];
    #pragma unroll
    for (int i = 0; i < 8; i++)
        #pragma unroll
        for (int q = 0; q < 4; q++) acc[i][q] = 0.0f;

    const int g = lane >> 3, r8 = lane & 7;
    const uint32_t a_row  = (uint32_t)(((g & 2) ? 8 : 0) + r8);
    const uint32_t a_col  = (uint32_t)(w * 16 + ((g & 1) ? 8 : 0));
    const uint32_t b_row  = (uint32_t)(((g & 1) ? 8 : 0) + r8);
    const uint32_t b_col8 = (uint32_t)((g & 2) ? 8 : 0);

    load_chunk(0);
    for (int ch = 0; ch < 16; ch++) {
        if (ch + 1 < 16) load_chunk(ch + 1);
        else cp_commit();
        cp_wait<1>();
        __syncthreads();
        uint32_t vb = sb + (uint32_t)(ch & 1) * KV_STG;
        uint32_t kb = vb + KV_VSZ;
        if (w < 5) {
            #pragma unroll
            for (int j = 0; j < 2; j++) {
                uint32_t a[4];
                ldsm4t(a[0], a[1], a[2], a[3],
                       vb + (a_row + j * 16) * KV_VROWB + a_col * 2);
                #pragma unroll
                for (int t = 0; t < 4; t++) {
                    uint32_t bb[4];
                    ldsm4t(bb[0], bb[1], bb[2], bb[3],
                           kb + (b_row + j * 16) * KV_KROWB + (16 * t + b_col8) * 2);
                    mma16816(acc[2 * t],     a, bb[0], bb[1]);
                    mma16816(acc[2 * t + 1], a, bb[2], bb[3]);
                }
            }
        }
        __syncthreads();
    }

    if (w < 4) {
        float* kvp = g_KVP + ((size_t)sc * 64 + bh) * 4096;
        int mm = w * 16 + (lane >> 2);
        int c0 = (lane & 3) * 2;
        #pragma unroll
        for (int t = 0; t < 4; t++)
            #pragma unroll
            for (int hf = 0; hf < 2; hf++) {
                int col = 16 * t + 8 * hf + c0;
                float* f = acc[2 * t + hf];
                kvp[mm * 64 + col]           = f[0];
                kvp[mm * 64 + col + 1]       = f[1];
                kvp[(mm + 8) * 64 + col]     = f[2];
                kvp[(mm + 8) * 64 + col + 1] = f[3];
            }
    } else if (w == 4 && (lane >> 2) == 0) {
        float* ksp = g_KSP + ((size_t)sc * 64 + bh) * 64;
        int c0 = (lane & 3) * 2;
        #pragma unroll
        for (int t = 0; t < 4; t++)
            #pragma unroll
            for (int hf = 0; hf < 2; hf++) {
                int col = 16 * t + 8 * hf + c0;
                ksp[col]     = acc[2 * t + hf][0];
                ksp[col + 1] = acc[2 * t + hf][1];
            }
    }
}

// ---------------------------------------------------------------------------
// Reduce partials -> attn B operand (fp16 hi/lo split)
// ---------------------------------------------------------------------------
__global__ void kv_reduce() {
    int i = blockIdx.x * 256 + threadIdx.x;
    if (i < 262144) {
        float s = 0.f;
        #pragma unroll
        for (int sc = 0; sc < NSC; sc++) s += g_KVP[sc * 262144 + i];
        int bh = i >> 12, md = i & 4095;
        __half hi = __float2half(s);
        __half lo = __float2half(s - __half2float(hi));
        size_t base = (size_t)bh * 8704;
        g_Battn[base + md] = hi;
        g_Battn[base + 4096 + md] = lo;
    } else {
        int j = i - 262144;
        float s = 0.f;
        #pragma unroll
        for (int sc = 0; sc < NSC; sc++) s += g_KSP[sc * 4096 + j];
        int bh = j >> 6, d = j & 63;
        __half hi = __float2half(s);
        __half lo = __float2half(s - __half2float(hi));
        size_t base = (size_t)bh * 8704;
        g_Battn[base + 128 * 64 + d] = hi;
        g_Battn[base + 129 * 64 + d] = lo;
    }
}

// ---------------------------------------------------------------------------
// Attention apply via HMMA (R11 proven)
// ---------------------------------------------------------------------------
#define AT_ROWB 144u
#define AT_ASZ  (128u * AT_ROWB)
#define AT_BSZ  (144u * AT_ROWB)

__global__ void __launch_bounds__(256)
attn_mma(const __half* __restrict__ QKV, const __half* __restrict__ Bt,
         __half* __restrict__ A2)
{
    __shared__ __align__(16) char smem[AT_ASZ + AT_BSZ];
    const uint32_t sb  = (uint32_t)__cvta_generic_to_shared(smem);
    const uint32_t sbB = sb + AT_ASZ;
    const int tid = threadIdx.x;
    const int w = tid >> 5, lane = tid & 31;
    const int bh = blockIdx.x >> 6, lt = blockIdx.x & 63;
    const int b = bh >> 3, h = bh & 7;

    for (int idx = tid; idx < 1024; idx += 256) {
        int r = idx >> 3, c = idx & 7;
        cp16(sb + (uint32_t)r * AT_ROWB + c * 16,
             QKV + ((size_t)(b * 8192 + lt * 128 + r)) * D3_ + h * 64 + c * 8);
    }
    for (int idx = tid; idx < 1088; idx += 256) {
        int r = idx >> 3, c = idx & 7;
        cp16(sbB + (uint32_t)r * AT_ROWB + c * 16,
             Bt + (size_t)bh * 8704 + r * 64 + c * 8);
    }
    cp_commit();
    cp_wait<0>();
    __syncthreads();

    const uint32_t aoff = sb + (uint32_t)(w * 16 + (lane & 15)) * AT_ROWB +
                          (uint32_t)(lane >> 4) * 16;
    const uint32_t boff = sbB + (uint32_t)(((lane >> 4) << 3) + (lane & 7)) * AT_ROWB +
                          (uint32_t)((lane >> 3) & 1) * 16;

    float acc[17][4];
    #pragma unroll
    for (int i = 0; i < 17; i++)
        #pragma unroll
        for (int q = 0; q < 4; q++) acc[i][q] = 0.0f;

    #pragma unroll
    for (int s = 0; s < 4; s++) {
        uint32_t a[4];
        ldsm4(a[0], a[1], a[2], a[3], aoff + s * 32);
        #pragma unroll
        for (int p = 0; p < 9; p++) {
            uint32_t bb[4];
            ldsm4(bb[0], bb[1], bb[2], bb[3], boff + (uint32_t)p * 16 * AT_ROWB + s * 32);
            mma16816(acc[2 * p], a, bb[0], bb[1]);
            if (p < 8) mma16816(acc[2 * p + 1], a, bb[2], bb[3]);
        }
    }

    float v0 = acc[16][0] + acc[16][1];
    float v1 = acc[16][2] + acc[16][3];
    float zd0 = __shfl_sync(0xffffffffu, v0, lane & 0x1C);
    float zd1 = __shfl_sync(0xffffffffu, v1, lane & 0x1C);
    float z0 = 1.0f / (zd0 + EPS_);
    float z1 = 1.0f / (zd1 + EPS_);

    size_t row0 = (size_t)(b * 8192 + lt * 128 + w * 16 + (lane >> 2));
    int colb = h * 64 + (lane & 3) * 2;
    #pragma unroll
    for (int nb = 0; nb < 8; nb++) {
        __half2 o0 = __floats2half2_rn((acc[nb][0] + acc[nb + 8][0]) * z0,
                                       (acc[nb][1] + acc[nb + 8][1]) * z0);
        __half2 o1 = __floats2half2_rn((acc[nb][2] + acc[nb + 8][2]) * z1,
                                       (acc[nb][3] + acc[nb + 8][3]) * z1);
        *reinterpret_cast<__half2*>(A2 + row0 * D_ + colb + nb * 8)       = o0;
        *reinterpret_cast<__half2*>(A2 + (row0 + 8) * D_ + colb + nb * 8) = o1;
    }
}

// ---------------------------------------------------------------------------
// Launch
// ---------------------------------------------------------------------------
extern "C" void kernel_launch(void* const* d_in, const int* in_sizes, int n_in,
                              void* d_out, int out_size) {
    const float* q     = (const float*)d_in[0];
    const float* k     = (const float*)d_in[1];
    const float* v     = (const float*)d_in[2];
    const float* w_qkv = (const float*)d_in[3];
    const float* w_out = (const float*)d_in[4];
    const float* b_out = (const float*)d_in[5];
    float* out = (float*)d_out;

    __half *A1, *W1, *A2, *W2, *QKV, *Bt;
    cudaGetSymbolAddress((void**)&A1,  g_A1);
    cudaGetSymbolAddress((void**)&W1,  g_W1);
    cudaGetSymbolAddress((void**)&A2,  g_A2);
    cudaGetSymbolAddress((void**)&W2,  g_W2);
    cudaGetSymbolAddress((void**)&QKV, g_QKV);
    cudaGetSymbolAddress((void**)&Bt,  g_Battn);

    cudaFuncSetAttribute(gemm1_bk64, cudaFuncAttributeMaxDynamicSharedMemorySize, B64_SMEM);
    cudaFuncSetAttribute(gemm_h16,   cudaFuncAttributeMaxDynamicSharedMemorySize, GSMEM);

    // 1) fp16 conversions
    conv1_k<<<98304, 256>>>((const float4*)q, (const float4*)k, (const float4*)v);
    convw_k<<<2304, 256>>>(w_qkv, W1);
    convw_k<<<256, 256>>>(w_out, W2);

    // 2) QKV(fp16) = elu-fused X @ W_qkv^T  (BK=64, half the barriers)
    gemm1_bk64<<<512 * 12, 256, B64_SMEM>>>(A1, W1, QKV);

    // 3) kv state (HMMA) -> reduce -> attention via HMMA
    kv_mma<<<dim3(64, NSC), 256>>>(QKV);
    kv_reduce<<<1040, 256>>>();
    attn_mma<<<4096, 256>>>(QKV, Bt, A2);

    // 4) out = A2 @ W2^T + b_out
    gemm_h16<<<512 * 4, 256, GSMEM>>>(A2, W2, out, b_out, 512, 4, 512);
}

// round 16
// speedup vs baseline: 1.2574x; 1.2574x over previous
#include <cuda_runtime.h>
#include <cuda_fp16.h>
#include <math.h>
#include <stdint.h>

#define B_   8
#define L_   8192
#define D_   512
#define H_   8
#define D3_  1536
#define M_   (B_ * L_)
#define EPS_ 1e-6f
#define NSC  16
#define SCHUNK (L_ / NSC)

// ---------------------------------------------------------------------------
// Scratch
// ---------------------------------------------------------------------------
__device__ __half g_A1 [(size_t)M_ * D3_];
__device__ __half g_W1 [(size_t)D3_ * D3_];
__device__ __half g_QKV[(size_t)M_ * D3_];
__device__ __half g_A2 [(size_t)M_ * D_];
__device__ __half g_W2 [(size_t)D_ * D_];
__device__ float g_KVP[NSC * 64 * 64 * 64];
__device__ float g_KSP[NSC * 64 * 64];
__device__ __half g_Battn[(size_t)64 * 136 * 64];

// ---------------------------------------------------------------------------
// PTX helpers
// ---------------------------------------------------------------------------
__device__ __forceinline__ void cp16(uint32_t dst, const void* src) {
    asm volatile("cp.async.cg.shared.global [%0], [%1], 16;" :: "r"(dst), "l"(src) : "memory");
}
__device__ __forceinline__ void cp_commit() {
    asm volatile("cp.async.commit_group;" ::: "memory");
}
template <int N>
__device__ __forceinline__ void cp_wait() {
    asm volatile("cp.async.wait_group %0;" :: "n"(N) : "memory");
}
__device__ __forceinline__ void ldsm4(uint32_t& r0, uint32_t& r1, uint32_t& r2, uint32_t& r3,
                                      uint32_t addr) {
    asm volatile("ldmatrix.sync.aligned.m8n8.x4.shared.b16 {%0,%1,%2,%3}, [%4];"
                 : "=r"(r0), "=r"(r1), "=r"(r2), "=r"(r3) : "r"(addr));
}
__device__ __forceinline__ void ldsm4t(uint32_t& r0, uint32_t& r1, uint32_t& r2, uint32_t& r3,
                                       uint32_t addr) {
    asm volatile("ldmatrix.sync.aligned.m8n8.x4.trans.shared.b16 {%0,%1,%2,%3}, [%4];"
                 : "=r"(r0), "=r"(r1), "=r"(r2), "=r"(r3) : "r"(addr));
}
__device__ __forceinline__ void mma16816(float* d, const uint32_t* a, uint32_t b0, uint32_t b1) {
    asm("mma.sync.aligned.m16n8k16.row.col.f32.f16.f16.f32 "
        "{%0,%1,%2,%3}, {%4,%5,%6,%7}, {%8,%9}, {%0,%1,%2,%3};"
        : "+f"(d[0]), "+f"(d[1]), "+f"(d[2]), "+f"(d[3])
        : "r"(a[0]), "r"(a[1]), "r"(a[2]), "r"(a[3]), "r"(b0), "r"(b1));
}
__device__ __forceinline__ float elu1(float x) {
    return x > 0.0f ? x + 1.0f : expf(x);
}

// ---------------------------------------------------------------------------
// GEMM1 (R13 skeleton, 5-stage pipeline): QKV = elu-fused A1 @ W1^T
// CTA 128x128, BK=32, 8 warps (4m x 2n), warp 32x64, staggered s-steps.
// ---------------------------------------------------------------------------
#define G1_STG  5
#define ROWB    80u
#define TILEB   (128u * ROWB)
#define STGB    (2u * TILEB)
#define G1SMEM  (G1_STG * STGB)     // 102400

__global__ void __launch_bounds__(256, 2)
gemm1_h(const __half* __restrict__ A, const __half* __restrict__ Bw,
        __half* __restrict__ Ch)
{
    extern __shared__ char smem[];
    const uint32_t sb = (uint32_t)__cvta_generic_to_shared(smem);
    const int tid = threadIdx.x;
    const int w = tid >> 5, lane = tid & 31;
    const int mt = blockIdx.x / 12, nt = blockIdx.x % 12;
    const int wm = w & 3, wn = w >> 2;
    const uint32_t stag = (uint32_t)(w & 1) * 32;

    const __half* Ab = A  + (size_t)(mt * 128) * 1536;
    const __half* Bb = Bw + (size_t)(nt * 128) * 1536;

    const int r0c = tid >> 2,         c0c = tid & 3;
    const int r1c = (tid + 256) >> 2, c1c = c0c;

    const uint32_t aoff = (uint32_t)(wm * 32 + (lane & 15)) * ROWB + (uint32_t)(lane >> 4) * 16;
    const uint32_t boff = TILEB +
        (uint32_t)(wn * 64 + ((lane >> 4) << 3) + (lane & 7)) * ROWB +
        (uint32_t)((lane >> 3) & 1) * 16;

    float acc[2][8][4];
    #pragma unroll
    for (int i = 0; i < 2; i++)
        #pragma unroll
        for (int j = 0; j < 8; j++)
            #pragma unroll
            for (int q = 0; q < 4; q++) acc[i][j][q] = 0.0f;

    auto load_stage = [&](int kt, int slot) {
        uint32_t base = sb + (uint32_t)slot * STGB;
        int k0 = kt * 32;
        cp16(base + r0c * ROWB + c0c * 16,         Ab + (size_t)r0c * 1536 + k0 + c0c * 8);
        cp16(base + r1c * ROWB + c1c * 16,         Ab + (size_t)r1c * 1536 + k0 + c1c * 8);
        cp16(base + TILEB + r0c * ROWB + c0c * 16, Bb + (size_t)r0c * 1536 + k0 + c0c * 8);
        cp16(base + TILEB + r1c * ROWB + c1c * 16, Bb + (size_t)r1c * 1536 + k0 + c1c * 8);
        cp_commit();
    };

    load_stage(0, 0);
    load_stage(1, 1);
    load_stage(2, 2);
    load_stage(3, 3);

    int cons = 0;                 // consume slot (rotates 0..4)
    int prod = 4;                 // produce slot
    for (int kt = 0; kt < 48; kt++) {
        cp_wait<3>();
        __syncthreads();
        if (kt + 4 < 48) load_stage(kt + 4, prod);
        else cp_commit();
        if (++prod == G1_STG) prod = 0;

        uint32_t base = sb + (uint32_t)cons * STGB;
        if (++cons == G1_STG) cons = 0;
        #pragma unroll
        for (int s = 0; s < 2; s++) {
            uint32_t so = ((uint32_t)s * 32) ^ stag;
            uint32_t a[2][4], b[4][4];
            ldsm4(a[0][0], a[0][1], a[0][2], a[0][3], base + aoff + so);
            ldsm4(a[1][0], a[1][1], a[1][2], a[1][3], base + aoff + 16 * ROWB + so);
            #pragma unroll
            for (int nb = 0; nb < 4; nb++)
                ldsm4(b[nb][0], b[nb][1], b[nb][2], b[nb][3],
                      base + boff + (uint32_t)nb * 16 * ROWB + so);
            #pragma unroll
            for (int mi = 0; mi < 2; mi++)
                #pragma unroll
                for (int ni = 0; ni < 8; ni++)
                    mma16816(acc[mi][ni], a[mi],
                             b[ni >> 1][(ni & 1) * 2], b[ni >> 1][(ni & 1) * 2 + 1]);
        }
    }

    const int mrow = mt * 128 + wm * 32 + (lane >> 2);
    const int ncol = nt * 128 + wn * 64 + (lane & 3) * 2;
    #pragma unroll
    for (int mi = 0; mi < 2; mi++) {
        #pragma unroll
        for (int ni = 0; ni < 8; ni++) {
            int col = ncol + ni * 8;
            float x0 = acc[mi][ni][0], x1 = acc[mi][ni][1];
            float x2 = acc[mi][ni][2], x3 = acc[mi][ni][3];
            if (col < 1024)     { x0 = elu1(x0); x2 = elu1(x2); }
            if (col + 1 < 1024) { x1 = elu1(x1); x3 = elu1(x3); }
            int row = mrow + mi * 16;
            __half2* p0 = reinterpret_cast<__half2*>(Ch + (size_t)row * 1536 + col);
            __half2* p1 = reinterpret_cast<__half2*>(Ch + (size_t)(row + 8) * 1536 + col);
            *p0 = __floats2half2_rn(x0, x1);
            *p1 = __floats2half2_rn(x2, x3);
        }
    }
}

// ---------------------------------------------------------------------------
// GEMM2 (R13 frozen): out = A2 @ W2^T + bias (fp32)
// ---------------------------------------------------------------------------
#define STAGES 4
#define GSMEM  (STAGES * STGB)

__global__ void __launch_bounds__(256, 2)
gemm_h16(const __half* __restrict__ A, const __half* __restrict__ Bw,
         float* __restrict__ C, const float* __restrict__ bias,
         int K, int NT, int Nout)
{
    extern __shared__ char smem[];
    const uint32_t sb = (uint32_t)__cvta_generic_to_shared(smem);
    const int tid = threadIdx.x;
    const int w = tid >> 5, lane = tid & 31;
    const int mt = blockIdx.x / NT, nt = blockIdx.x % NT;
    const int wm = w & 3, wn = w >> 2;
    const int ktiles = K >> 5;
    const uint32_t stag = (uint32_t)(w & 1) * 32;

    const __half* Ab = A  + (size_t)(mt * 128) * K;
    const __half* Bb = Bw + (size_t)(nt * 128) * K;

    const int r0c = tid >> 2,         c0c = tid & 3;
    const int r1c = (tid + 256) >> 2, c1c = c0c;

    const uint32_t aoff = (uint32_t)(wm * 32 + (lane & 15)) * ROWB + (uint32_t)(lane >> 4) * 16;
    const uint32_t boff = TILEB +
        (uint32_t)(wn * 64 + ((lane >> 4) << 3) + (lane & 7)) * ROWB +
        (uint32_t)((lane >> 3) & 1) * 16;

    float acc[2][8][4];
    #pragma unroll
    for (int i = 0; i < 2; i++)
        #pragma unroll
        for (int j = 0; j < 8; j++)
            #pragma unroll
            for (int q = 0; q < 4; q++) acc[i][j][q] = 0.0f;

    auto load_stage = [&](int kt) {
        uint32_t base = sb + (uint32_t)(kt & (STAGES - 1)) * STGB;
        int k0 = kt * 32;
        cp16(base + r0c * ROWB + c0c * 16,         Ab + (size_t)r0c * K + k0 + c0c * 8);
        cp16(base + r1c * ROWB + c1c * 16,         Ab + (size_t)r1c * K + k0 + c1c * 8);
        cp16(base + TILEB + r0c * ROWB + c0c * 16, Bb + (size_t)r0c * K + k0 + c0c * 8);
        cp16(base + TILEB + r1c * ROWB + c1c * 16, Bb + (size_t)r1c * K + k0 + c1c * 8);
        cp_commit();
    };

    load_stage(0);
    load_stage(1);
    load_stage(2);

    for (int kt = 0; kt < ktiles; kt++) {
        cp_wait<STAGES - 2>();
        __syncthreads();
        if (kt + STAGES - 1 < ktiles) load_stage(kt + STAGES - 1);
        else cp_commit();

        uint32_t base = sb + (uint32_t)(kt & (STAGES - 1)) * STGB;
        #pragma unroll
        for (int s = 0; s < 2; s++) {
            uint32_t so = ((uint32_t)s * 32) ^ stag;
            uint32_t a[2][4], b[4][4];
            ldsm4(a[0][0], a[0][1], a[0][2], a[0][3], base + aoff + so);
            ldsm4(a[1][0], a[1][1], a[1][2], a[1][3], base + aoff + 16 * ROWB + so);
            #pragma unroll
            for (int nb = 0; nb < 4; nb++)
                ldsm4(b[nb][0], b[nb][1], b[nb][2], b[nb][3],
                      base + boff + (uint32_t)nb * 16 * ROWB + so);
            #pragma unroll
            for (int mi = 0; mi < 2; mi++)
                #pragma unroll
                for (int ni = 0; ni < 8; ni++)
                    mma16816(acc[mi][ni], a[mi],
                             b[ni >> 1][(ni & 1) * 2], b[ni >> 1][(ni & 1) * 2 + 1]);
        }
    }

    const int mrow = mt * 128 + wm * 32 + (lane >> 2);
    const int ncol = nt * 128 + wn * 64 + (lane & 3) * 2;
    #pragma unroll
    for (int mi = 0; mi < 2; mi++) {
        #pragma unroll
        for (int ni = 0; ni < 8; ni++) {
            int col = ncol + ni * 8;
            float bv0 = bias[col], bv1 = bias[col + 1];
            int row = mrow + mi * 16;
            float2* p0 = reinterpret_cast<float2*>(C + (size_t)row * Nout + col);
            float2* p1 = reinterpret_cast<float2*>(C + (size_t)(row + 8) * Nout + col);
            *p0 = make_float2(acc[mi][ni][0] + bv0, acc[mi][ni][1] + bv1);
            *p1 = make_float2(acc[mi][ni][2] + bv0, acc[mi][ni][3] + bv1);
        }
    }
}

// ---------------------------------------------------------------------------
// Conversions fp32 -> fp16
// ---------------------------------------------------------------------------
__device__ __forceinline__ uint2 pack4h(float4 s) {
    __half2 h0 = __floats2half2_rn(s.x, s.y);
    __half2 h1 = __floats2half2_rn(s.z, s.w);
    uint2 r;
    r.x = *reinterpret_cast<uint32_t*>(&h0);
    r.y = *reinterpret_cast<uint32_t*>(&h1);
    return r;
}

__global__ void conv1_k(const float4* __restrict__ q, const float4* __restrict__ k,
                        const float4* __restrict__ v) {
    int i = blockIdx.x * 256 + threadIdx.x;
    int seg = i >> 23;
    int r   = i & ((1 << 23) - 1);
    int n   = r >> 7;
    int c4  = r & 127;
    const float4* src = (seg == 0) ? q : (seg == 1) ? k : v;
    float4 s = src[r];
    uint2* dst = reinterpret_cast<uint2*>(g_A1) + (size_t)n * 384 + seg * 128 + c4;
    *dst = pack4h(s);
}

__global__ void convw_k(const float* __restrict__ W, __half* __restrict__ Wd) {
    int i = blockIdx.x * 256 + threadIdx.x;
    float4 s = reinterpret_cast<const float4*>(W)[i];
    *reinterpret_cast<uint2*>(Wd + (size_t)i * 4) = pack4h(s);
}

// ---------------------------------------------------------------------------
// kv state via HMMA (R12 proven)
// ---------------------------------------------------------------------------
#define KV_VROWB 176u
#define KV_KROWB 144u
#define KV_VSZ   (32u * KV_VROWB)
#define KV_STG   (KV_VSZ + 32u * KV_KROWB)

__global__ void __launch_bounds__(256)
kv_mma(const __half* __restrict__ QKV) {
    __shared__ __align__(16) char smem[2 * KV_STG];
    const uint32_t sb = (uint32_t)__cvta_generic_to_shared(smem);
    const int bh = blockIdx.x, sc = blockIdx.y;
    const int b = bh >> 3, h = bh & 7;
    const int tid = threadIdx.x;
    const int w = tid >> 5, lane = tid & 31;

    for (int i = tid; i < 1024; i += 256) {
        int st = i >> 9, r = (i >> 4) & 31, c = i & 15;
        *reinterpret_cast<__half*>(smem + st * KV_STG + r * KV_VROWB + (64 + c) * 2) =
            __float2half(c == 0 ? 1.0f : 0.0f);
    }
    __syncthreads();

    const size_t rowg0 = (size_t)b * 8192 + (size_t)sc * SCHUNK;

    auto load_chunk = [&](int ch) {
        uint32_t base = sb + (uint32_t)(ch & 1) * KV_STG;
        #pragma unroll
        for (int o = tid; o < 512; o += 256) {
            int r = o >> 4, c = o & 15;
            size_t grow = (rowg0 + ch * 32 + r) * (size_t)D3_;
            if (c < 8)
                cp16(base + r * KV_VROWB + c * 16,
                     QKV + grow + 1024 + h * 64 + c * 8);
            else
                cp16(base + KV_VSZ + r * KV_KROWB + (c - 8) * 16,
                     QKV + grow + 512 + h * 64 + (c - 8) * 8);
        }
        cp_commit();
    };

    float acc[8][4];
    #pragma unroll
    for (int i = 0; i < 8; i++)
        #pragma unroll
        for (int q = 0; q < 4; q++) acc[i][q] = 0.0f;

    const int g = lane >> 3, r8 = lane & 7;
    const uint32_t a_row  = (uint32_t)(((g & 2) ? 8 : 0) + r8);
    const uint32_t a_col  = (uint32_t)(w * 16 + ((g & 1) ? 8 : 0));
    const uint32_t b_row  = (uint32_t)(((g & 1) ? 8 : 0) + r8);
    const uint32_t b_col8 = (uint32_t)((g & 2) ? 8 : 0);

    load_chunk(0);
    for (int ch = 0; ch < 16; ch++) {
        if (ch + 1 < 16) load_chunk(ch + 1);
        else cp_commit();
        cp_wait<1>();
        __syncthreads();
        uint32_t vb = sb + (uint32_t)(ch & 1) * KV_STG;
        uint32_t kb = vb + KV_VSZ;
        if (w < 5) {
            #pragma unroll
            for (int j = 0; j < 2; j++) {
                uint32_t a[4];
                ldsm4t(a[0], a[1], a[2], a[3],
                       vb + (a_row + j * 16) * KV_VROWB + a_col * 2);
                #pragma unroll
                for (int t = 0; t < 4; t++) {
                    uint32_t bb[4];
                    ldsm4t(bb[0], bb[1], bb[2], bb[3],
                           kb + (b_row + j * 16) * KV_KROWB + (16 * t + b_col8) * 2);
                    mma16816(acc[2 * t],     a, bb[0], bb[1]);
                    mma16816(acc[2 * t + 1], a, bb[2], bb[3]);
                }
            }
        }
        __syncthreads();
    }

    if (w < 4) {
        float* kvp = g_KVP + ((size_t)sc * 64 + bh) * 4096;
        int mm = w * 16 + (lane >> 2);
        int c0 = (lane & 3) * 2;
        #pragma unroll
        for (int t = 0; t < 4; t++)
            #pragma unroll
            for (int hf = 0; hf < 2; hf++) {
                int col = 16 * t + 8 * hf + c0;
                float* f = acc[2 * t + hf];
                kvp[mm * 64 + col]           = f[0];
                kvp[mm * 64 + col + 1]       = f[1];
                kvp[(mm + 8) * 64 + col]     = f[2];
                kvp[(mm + 8) * 64 + col + 1] = f[3];
            }
    } else if (w == 4 && (lane >> 2) == 0) {
        float* ksp = g_KSP + ((size_t)sc * 64 + bh) * 64;
        int c0 = (lane & 3) * 2;
        #pragma unroll
        for (int t = 0; t < 4; t++)
            #pragma unroll
            for (int hf = 0; hf < 2; hf++) {
                int col = 16 * t + 8 * hf + c0;
                ksp[col]     = acc[2 * t + hf][0];
                ksp[col + 1] = acc[2 * t + hf][1];
            }
    }
}

// ---------------------------------------------------------------------------
// Reduce partials -> attn B operand (fp16 hi/lo split)
// ---------------------------------------------------------------------------
__global__ void kv_reduce() {
    int i = blockIdx.x * 256 + threadIdx.x;
    if (i < 262144) {
        float s = 0.f;
        #pragma unroll
        for (int sc = 0; sc < NSC; sc++) s += g_KVP[sc * 262144 + i];
        int bh = i >> 12, md = i & 4095;
        __half hi = __float2half(s);
        __half lo = __float2half(s - __half2float(hi));
        size_t base = (size_t)bh * 8704;
        g_Battn[base + md] = hi;
        g_Battn[base + 4096 + md] = lo;
    } else {
        int j = i - 262144;
        float s = 0.f;
        #pragma unroll
        for (int sc = 0; sc < NSC; sc++) s += g_KSP[sc * 4096 + j];
        int bh = j >> 6, d = j & 63;
        __half hi = __float2half(s);
        __half lo = __float2half(s - __half2float(hi));
        size_t base = (size_t)bh * 8704;
        g_Battn[base + 128 * 64 + d] = hi;
        g_Battn[base + 129 * 64 + d] = lo;
    }
}

// ---------------------------------------------------------------------------
// Attention apply via HMMA (R11 mappings; 2 row-tiles per block, B loaded once)
// ---------------------------------------------------------------------------
#define AT_ROWB 144u
#define AT_ASZ  (128u * AT_ROWB)
#define AT_BSZ  (144u * AT_ROWB)

__global__ void __launch_bounds__(256)
attn_mma(const __half* __restrict__ QKV, const __half* __restrict__ Bt,
         __half* __restrict__ A2)
{
    __shared__ __align__(16) char smem[AT_ASZ + AT_BSZ];
    const uint32_t sb  = (uint32_t)__cvta_generic_to_shared(smem);
    const uint32_t sbB = sb + AT_ASZ;
    const int tid = threadIdx.x;
    const int w = tid >> 5, lane = tid & 31;
    const int bh = blockIdx.x >> 5, ltp = blockIdx.x & 31;   // 2048 blocks
    const int b = bh >> 3, h = bh & 7;

    // B loaded once per block (serves both row-tiles)
    for (int idx = tid; idx < 1088; idx += 256) {
        int r = idx >> 3, c = idx & 7;
        cp16(sbB + (uint32_t)r * AT_ROWB + c * 16,
             Bt + (size_t)bh * 8704 + r * 64 + c * 8);
    }
    cp_commit();

    const uint32_t aoff = sb + (uint32_t)(w * 16 + (lane & 15)) * AT_ROWB +
                          (uint32_t)(lane >> 4) * 16;
    const uint32_t boff = sbB + (uint32_t)(((lane >> 4) << 3) + (lane & 7)) * AT_ROWB +
                          (uint32_t)((lane >> 3) & 1) * 16;

    for (int tt = 0; tt < 2; tt++) {
        const int lt = ltp * 2 + tt;
        for (int idx = tid; idx < 1024; idx += 256) {
            int r = idx >> 3, c = idx & 7;
            cp16(sb + (uint32_t)r * AT_ROWB + c * 16,
                 QKV + ((size_t)(b * 8192 + lt * 128 + r)) * D3_ + h * 64 + c * 8);
        }
        cp_commit();
        cp_wait<0>();
        __syncthreads();

        float acc[17][4];
        #pragma unroll
        for (int i = 0; i < 17; i++)
            #pragma unroll
            for (int q = 0; q < 4; q++) acc[i][q] = 0.0f;

        #pragma unroll
        for (int s = 0; s < 4; s++) {
            uint32_t a[4];
            ldsm4(a[0], a[1], a[2], a[3], aoff + s * 32);
            #pragma unroll
            for (int p = 0; p < 9; p++) {
                uint32_t bb[4];
                ldsm4(bb[0], bb[1], bb[2], bb[3], boff + (uint32_t)p * 16 * AT_ROWB + s * 32);
                mma16816(acc[2 * p], a, bb[0], bb[1]);
                if (p < 8) mma16816(acc[2 * p + 1], a, bb[2], bb[3]);
            }
        }

        float v0 = acc[16][0] + acc[16][1];
        float v1 = acc[16][2] + acc[16][3];
        float zd0 = __shfl_sync(0xffffffffu, v0, lane & 0x1C);
        float zd1 = __shfl_sync(0xffffffffu, v1, lane & 0x1C);
        float z0 = 1.0f / (zd0 + EPS_);
        float z1 = 1.0f / (zd1 + EPS_);

        size_t row0 = (size_t)(b * 8192 + lt * 128 + w * 16 + (lane >> 2));
        int colb = h * 64 + (lane & 3) * 2;
        #pragma unroll
        for (int nb = 0; nb < 8; nb++) {
            __half2 o0 = __floats2half2_rn((acc[nb][0] + acc[nb + 8][0]) * z0,
                                           (acc[nb][1] + acc[nb + 8][1]) * z0);
            __half2 o1 = __floats2half2_rn((acc[nb][2] + acc[nb + 8][2]) * z1,
                                           (acc[nb][3] + acc[nb + 8][3]) * z1);
            *reinterpret_cast<__half2*>(A2 + row0 * D_ + colb + nb * 8)       = o0;
            *reinterpret_cast<__half2*>(A2 + (row0 + 8) * D_ + colb + nb * 8) = o1;
        }
        __syncthreads();   // LDSMs done before next tt overwrites A tile
    }
}

// ---------------------------------------------------------------------------
// Launch
// ---------------------------------------------------------------------------
extern "C" void kernel_launch(void* const* d_in, const int* in_sizes, int n_in,
                              void* d_out, int out_size) {
    const float* q     = (const float*)d_in[0];
    const float* k     = (const float*)d_in[1];
    const float* v     = (const float*)d_in[2];
    const float* w_qkv = (const float*)d_in[3];
    const float* w_out = (const float*)d_in[4];
    const float* b_out = (const float*)d_in[5];
    float* out = (float*)d_out;

    __half *A1, *W1, *A2, *W2, *QKV, *Bt;
    cudaGetSymbolAddress((void**)&A1,  g_A1);
    cudaGetSymbolAddress((void**)&W1,  g_W1);
    cudaGetSymbolAddress((void**)&A2,  g_A2);
    cudaGetSymbolAddress((void**)&W2,  g_W2);
    cudaGetSymbolAddress((void**)&QKV, g_QKV);
    cudaGetSymbolAddress((void**)&Bt,  g_Battn);

    cudaFuncSetAttribute(gemm1_h,  cudaFuncAttributeMaxDynamicSharedMemorySize, G1SMEM);
    cudaFuncSetAttribute(gemm_h16, cudaFuncAttributeMaxDynamicSharedMemorySize, GSMEM);

    // 1) fp16 conversions
    conv1_k<<<98304, 256>>>((const float4*)q, (const float4*)k, (const float4*)v);
    convw_k<<<2304, 256>>>(w_qkv, W1);
    convw_k<<<256, 256>>>(w_out, W2);

    // 2) QKV(fp16) = elu-fused X @ W_qkv^T  (5-stage pipeline)
    gemm1_h<<<512 * 12, 256, G1SMEM>>>(A1, W1, QKV);

    // 3) kv state (HMMA) -> reduce -> attention via HMMA (2 tiles/block)
    kv_mma<<<dim3(64, NSC), 256>>>(QKV);
    kv_reduce<<<1040, 256>>>();
    attn_mma<<<2048, 256>>>(QKV, Bt, A2);

    // 4) out = A2 @ W2^T + b_out
    gemm_h16<<<512 * 4, 256, GSMEM>>>(A2, W2, out, b_out, 512, 4, 512);
}

// round 17
// speedup vs baseline: 1.2909x; 1.0267x over previous
#include <cuda_runtime.h>
#include <cuda_fp16.h>
#include <math.h>
#include <stdint.h>

#define B_   8
#define L_   8192
#define D_   512
#define H_   8
#define D3_  1536
#define M_   (B_ * L_)
#define EPS_ 1e-6f
#define NSC  16
#define SCHUNK (L_ / NSC)

// ---------------------------------------------------------------------------
// Scratch
// ---------------------------------------------------------------------------
__device__ __half g_A1 [(size_t)M_ * D3_];
__device__ __half g_W1 [(size_t)D3_ * D3_];
__device__ __half g_QKV[(size_t)M_ * D3_];
__device__ __half g_A2 [(size_t)M_ * D_];
__device__ __half g_W2 [(size_t)D_ * D_];
__device__ float g_KVP[NSC * 64 * 64 * 64];
__device__ float g_KSP[NSC * 64 * 64];
__device__ __half g_Battn[(size_t)64 * 136 * 64];

// ---------------------------------------------------------------------------
// PTX helpers
// ---------------------------------------------------------------------------
__device__ __forceinline__ void cp16(uint32_t dst, const void* src) {
    asm volatile("cp.async.cg.shared.global [%0], [%1], 16;" :: "r"(dst), "l"(src) : "memory");
}
__device__ __forceinline__ void cp_commit() {
    asm volatile("cp.async.commit_group;" ::: "memory");
}
template <int N>
__device__ __forceinline__ void cp_wait() {
    asm volatile("cp.async.wait_group %0;" :: "n"(N) : "memory");
}
__device__ __forceinline__ void ldsm4(uint32_t& r0, uint32_t& r1, uint32_t& r2, uint32_t& r3,
                                      uint32_t addr) {
    asm volatile("ldmatrix.sync.aligned.m8n8.x4.shared.b16 {%0,%1,%2,%3}, [%4];"
                 : "=r"(r0), "=r"(r1), "=r"(r2), "=r"(r3) : "r"(addr));
}
__device__ __forceinline__ void ldsm4t(uint32_t& r0, uint32_t& r1, uint32_t& r2, uint32_t& r3,
                                       uint32_t addr) {
    asm volatile("ldmatrix.sync.aligned.m8n8.x4.trans.shared.b16 {%0,%1,%2,%3}, [%4];"
                 : "=r"(r0), "=r"(r1), "=r"(r2), "=r"(r3) : "r"(addr));
}
__device__ __forceinline__ void mma16816(float* d, const uint32_t* a, uint32_t b0, uint32_t b1) {
    asm("mma.sync.aligned.m16n8k16.row.col.f32.f16.f16.f32 "
        "{%0,%1,%2,%3}, {%4,%5,%6,%7}, {%8,%9}, {%0,%1,%2,%3};"
        : "+f"(d[0]), "+f"(d[1]), "+f"(d[2]), "+f"(d[3])
        : "r"(a[0]), "r"(a[1]), "r"(a[2]), "r"(a[3]), "r"(b0), "r"(b1));
}
__device__ __forceinline__ float elu1(float x) {
    return x > 0.0f ? x + 1.0f : expf(x);
}

// ---------------------------------------------------------------------------
// HMMA GEMM (R13 frozen — best measured): C = A[M,K] @ Bw[Nout,K]^T
// CTA 128x128, BK=32, 4-stage cp.async, 8 warps (4m x 2n), warp 32x64,
// staggered s-steps. mode 0: elu+1 cols<1024 -> fp16 Ch. mode 1: +bias -> fp32 C.
// ---------------------------------------------------------------------------
#define STAGES 4
#define ROWB   80u
#define TILEB  (128u * ROWB)
#define STGB   (2u * TILEB)
#define GSMEM  (STAGES * STGB)

__global__ void __launch_bounds__(256, 2)
gemm_h(const __half* __restrict__ A, const __half* __restrict__ Bw,
       float* __restrict__ C, __half* __restrict__ Ch,
       const float* __restrict__ bias,
       int K, int NT, int Nout, int mode)
{
    extern __shared__ char smem[];
    const uint32_t sb = (uint32_t)__cvta_generic_to_shared(smem);
    const int tid = threadIdx.x;
    const int w = tid >> 5, lane = tid & 31;
    const int mt = blockIdx.x / NT, nt = blockIdx.x % NT;
    const int wm = w & 3, wn = w >> 2;
    const int ktiles = K >> 5;
    const uint32_t stag = (uint32_t)(w & 1) * 32;

    const __half* Ab = A  + (size_t)(mt * 128) * K;
    const __half* Bb = Bw + (size_t)(nt * 128) * K;

    const int r0c = tid >> 2,         c0c = tid & 3;
    const int r1c = (tid + 256) >> 2, c1c = c0c;

    const uint32_t aoff = (uint32_t)(wm * 32 + (lane & 15)) * ROWB + (uint32_t)(lane >> 4) * 16;
    const uint32_t boff = TILEB +
        (uint32_t)(wn * 64 + ((lane >> 4) << 3) + (lane & 7)) * ROWB +
        (uint32_t)((lane >> 3) & 1) * 16;

    float acc[2][8][4];
    #pragma unroll
    for (int i = 0; i < 2; i++)
        #pragma unroll
        for (int j = 0; j < 8; j++)
            #pragma unroll
            for (int q = 0; q < 4; q++) acc[i][j][q] = 0.0f;

    auto load_stage = [&](int kt) {
        uint32_t base = sb + (uint32_t)(kt & (STAGES - 1)) * STGB;
        int k0 = kt * 32;
        cp16(base + r0c * ROWB + c0c * 16,         Ab + (size_t)r0c * K + k0 + c0c * 8);
        cp16(base + r1c * ROWB + c1c * 16,         Ab + (size_t)r1c * K + k0 + c1c * 8);
        cp16(base + TILEB + r0c * ROWB + c0c * 16, Bb + (size_t)r0c * K + k0 + c0c * 8);
        cp16(base + TILEB + r1c * ROWB + c1c * 16, Bb + (size_t)r1c * K + k0 + c1c * 8);
        cp_commit();
    };

    load_stage(0);
    load_stage(1);
    load_stage(2);

    for (int kt = 0; kt < ktiles; kt++) {
        cp_wait<STAGES - 2>();
        __syncthreads();
        if (kt + STAGES - 1 < ktiles) load_stage(kt + STAGES - 1);
        else cp_commit();

        uint32_t base = sb + (uint32_t)(kt & (STAGES - 1)) * STGB;
        #pragma unroll
        for (int s = 0; s < 2; s++) {
            uint32_t so = ((uint32_t)s * 32) ^ stag;
            uint32_t a[2][4], b[4][4];
            ldsm4(a[0][0], a[0][1], a[0][2], a[0][3], base + aoff + so);
            ldsm4(a[1][0], a[1][1], a[1][2], a[1][3], base + aoff + 16 * ROWB + so);
            #pragma unroll
            for (int nb = 0; nb < 4; nb++)
                ldsm4(b[nb][0], b[nb][1], b[nb][2], b[nb][3],
                      base + boff + (uint32_t)nb * 16 * ROWB + so);
            #pragma unroll
            for (int mi = 0; mi < 2; mi++)
                #pragma unroll
                for (int ni = 0; ni < 8; ni++)
                    mma16816(acc[mi][ni], a[mi],
                             b[ni >> 1][(ni & 1) * 2], b[ni >> 1][(ni & 1) * 2 + 1]);
        }
    }

    const int mrow = mt * 128 + wm * 32 + (lane >> 2);
    const int ncol = nt * 128 + wn * 64 + (lane & 3) * 2;
    #pragma unroll
    for (int mi = 0; mi < 2; mi++) {
        #pragma unroll
        for (int ni = 0; ni < 8; ni++) {
            int col = ncol + ni * 8;
            float x0 = acc[mi][ni][0], x1 = acc[mi][ni][1];
            float x2 = acc[mi][ni][2], x3 = acc[mi][ni][3];
            int row = mrow + mi * 16;
            if (mode == 0) {
                if (col < 1024)     { x0 = elu1(x0); x2 = elu1(x2); }
                if (col + 1 < 1024) { x1 = elu1(x1); x3 = elu1(x3); }
                __half2* p0 = reinterpret_cast<__half2*>(Ch + (size_t)row * Nout + col);
                __half2* p1 = reinterpret_cast<__half2*>(Ch + (size_t)(row + 8) * Nout + col);
                *p0 = __floats2half2_rn(x0, x1);
                *p1 = __floats2half2_rn(x2, x3);
            } else {
                float bv0 = bias[col], bv1 = bias[col + 1];
                float2* p0 = reinterpret_cast<float2*>(C + (size_t)row * Nout + col);
                float2* p1 = reinterpret_cast<float2*>(C + (size_t)(row + 8) * Nout + col);
                *p0 = make_float2(x0 + bv0, x1 + bv1);
                *p1 = make_float2(x2 + bv0, x3 + bv1);
            }
        }
    }
}

// ---------------------------------------------------------------------------
// Conversions fp32 -> fp16
// ---------------------------------------------------------------------------
__device__ __forceinline__ uint2 pack4h(float4 s) {
    __half2 h0 = __floats2half2_rn(s.x, s.y);
    __half2 h1 = __floats2half2_rn(s.z, s.w);
    uint2 r;
    r.x = *reinterpret_cast<uint32_t*>(&h0);
    r.y = *reinterpret_cast<uint32_t*>(&h1);
    return r;
}

__global__ void conv1_k(const float4* __restrict__ q, const float4* __restrict__ k,
                        const float4* __restrict__ v) {
    int i = blockIdx.x * 256 + threadIdx.x;
    int seg = i >> 23;
    int r   = i & ((1 << 23) - 1);
    int n   = r >> 7;
    int c4  = r & 127;
    const float4* src = (seg == 0) ? q : (seg == 1) ? k : v;
    float4 s = src[r];
    uint2* dst = reinterpret_cast<uint2*>(g_A1) + (size_t)n * 384 + seg * 128 + c4;
    *dst = pack4h(s);
}

__global__ void convw_k(const float* __restrict__ W, __half* __restrict__ Wd) {
    int i = blockIdx.x * 256 + threadIdx.x;
    float4 s = reinterpret_cast<const float4*>(W)[i];
    *reinterpret_cast<uint2*>(Wd + (size_t)i * 4) = pack4h(s);
}

// ---------------------------------------------------------------------------
// kv state via HMMA (R12 proven)
// ---------------------------------------------------------------------------
#define KV_VROWB 176u
#define KV_KROWB 144u
#define KV_VSZ   (32u * KV_VROWB)
#define KV_STG   (KV_VSZ + 32u * KV_KROWB)

__global__ void __launch_bounds__(256)
kv_mma(const __half* __restrict__ QKV) {
    __shared__ __align__(16) char smem[2 * KV_STG];
    const uint32_t sb = (uint32_t)__cvta_generic_to_shared(smem);
    const int bh = blockIdx.x, sc = blockIdx.y;
    const int b = bh >> 3, h = bh & 7;
    const int tid = threadIdx.x;
    const int w = tid >> 5, lane = tid & 31;

    for (int i = tid; i < 1024; i += 256) {
        int st = i >> 9, r = (i >> 4) & 31, c = i & 15;
        *reinterpret_cast<__half*>(smem + st * KV_STG + r * KV_VROWB + (64 + c) * 2) =
            __float2half(c == 0 ? 1.0f : 0.0f);
    }
    __syncthreads();

    const size_t rowg0 = (size_t)b * 8192 + (size_t)sc * SCHUNK;

    auto load_chunk = [&](int ch) {
        uint32_t base = sb + (uint32_t)(ch & 1) * KV_STG;
        #pragma unroll
        for (int o = tid; o < 512; o += 256) {
            int r = o >> 4, c = o & 15;
            size_t grow = (rowg0 + ch * 32 + r) * (size_t)D3_;
            if (c < 8)
                cp16(base + r * KV_VROWB + c * 16,
                     QKV + grow + 1024 + h * 64 + c * 8);
            else
                cp16(base + KV_VSZ + r * KV_KROWB + (c - 8) * 16,
                     QKV + grow + 512 + h * 64 + (c - 8) * 8);
        }
        cp_commit();
    };

    float acc[8][4];
    #pragma unroll
    for (int i = 0; i < 8; i++)
        #pragma unroll
        for (int q = 0; q < 4; q++) acc[i][q] = 0.0f;

    const int g = lane >> 3, r8 = lane & 7;
    const uint32_t a_row  = (uint32_t)(((g & 2) ? 8 : 0) + r8);
    const uint32_t a_col  = (uint32_t)(w * 16 + ((g & 1) ? 8 : 0));
    const uint32_t b_row  = (uint32_t)(((g & 1) ? 8 : 0) + r8);
    const uint32_t b_col8 = (uint32_t)((g & 2) ? 8 : 0);

    load_chunk(0);
    for (int ch = 0; ch < 16; ch++) {
        if (ch + 1 < 16) load_chunk(ch + 1);
        else cp_commit();
        cp_wait<1>();
        __syncthreads();
        uint32_t vb = sb + (uint32_t)(ch & 1) * KV_STG;
        uint32_t kb = vb + KV_VSZ;
        if (w < 5) {
            #pragma unroll
            for (int j = 0; j < 2; j++) {
                uint32_t a[4];
                ldsm4t(a[0], a[1], a[2], a[3],
                       vb + (a_row + j * 16) * KV_VROWB + a_col * 2);
                #pragma unroll
                for (int t = 0; t < 4; t++) {
                    uint32_t bb[4];
                    ldsm4t(bb[0], bb[1], bb[2], bb[3],
                           kb + (b_row + j * 16) * KV_KROWB + (16 * t + b_col8) * 2);
                    mma16816(acc[2 * t],     a, bb[0], bb[1]);
                    mma16816(acc[2 * t + 1], a, bb[2], bb[3]);
                }
            }
        }
        __syncthreads();
    }

    if (w < 4) {
        float* kvp = g_KVP + ((size_t)sc * 64 + bh) * 4096;
        int mm = w * 16 + (lane >> 2);
        int c0 = (lane & 3) * 2;
        #pragma unroll
        for (int t = 0; t < 4; t++)
            #pragma unroll
            for (int hf = 0; hf < 2; hf++) {
                int col = 16 * t + 8 * hf + c0;
                float* f = acc[2 * t + hf];
                kvp[mm * 64 + col]           = f[0];
                kvp[mm * 64 + col + 1]       = f[1];
                kvp[(mm + 8) * 64 + col]     = f[2];
                kvp[(mm + 8) * 64 + col + 1] = f[3];
            }
    } else if (w == 4 && (lane >> 2) == 0) {
        float* ksp = g_KSP + ((size_t)sc * 64 + bh) * 64;
        int c0 = (lane & 3) * 2;
        #pragma unroll
        for (int t = 0; t < 4; t++)
            #pragma unroll
            for (int hf = 0; hf < 2; hf++) {
                int col = 16 * t + 8 * hf + c0;
                ksp[col]     = acc[2 * t + hf][0];
                ksp[col + 1] = acc[2 * t + hf][1];
            }
    }
}

// ---------------------------------------------------------------------------
// Reduce partials -> attn B operand (fp16 hi/lo split)
// ---------------------------------------------------------------------------
__global__ void kv_reduce() {
    int i = blockIdx.x * 256 + threadIdx.x;
    if (i < 262144) {
        float s = 0.f;
        #pragma unroll
        for (int sc = 0; sc < NSC; sc++) s += g_KVP[sc * 262144 + i];
        int bh = i >> 12, md = i & 4095;
        __half hi = __float2half(s);
        __half lo = __float2half(s - __half2float(hi));
        size_t base = (size_t)bh * 8704;
        g_Battn[base + md] = hi;
        g_Battn[base + 4096 + md] = lo;
    } else {
        int j = i - 262144;
        float s = 0.f;
        #pragma unroll
        for (int sc = 0; sc < NSC; sc++) s += g_KSP[sc * 4096 + j];
        int bh = j >> 6, d = j & 63;
        __half hi = __float2half(s);
        __half lo = __float2half(s - __half2float(hi));
        size_t base = (size_t)bh * 8704;
        g_Battn[base + 128 * 64 + d] = hi;
        g_Battn[base + 129 * 64 + d] = lo;
    }
}

// ---------------------------------------------------------------------------
// Attention apply via HMMA (R16 proven: 2 row-tiles/block, B loaded once)
// ---------------------------------------------------------------------------
#define AT_ROWB 144u
#define AT_ASZ  (128u * AT_ROWB)
#define AT_BSZ  (144u * AT_ROWB)

__global__ void __launch_bounds__(256)
attn_mma(const __half* __restrict__ QKV, const __half* __restrict__ Bt,
         __half* __restrict__ A2)
{
    __shared__ __align__(16) char smem[AT_ASZ + AT_BSZ];
    const uint32_t sb  = (uint32_t)__cvta_generic_to_shared(smem);
    const uint32_t sbB = sb + AT_ASZ;
    const int tid = threadIdx.x;
    const int w = tid >> 5, lane = tid & 31;
    const int bh = blockIdx.x >> 5, ltp = blockIdx.x & 31;
    const int b = bh >> 3, h = bh & 7;

    for (int idx = tid; idx < 1088; idx += 256) {
        int r = idx >> 3, c = idx & 7;
        cp16(sbB + (uint32_t)r * AT_ROWB + c * 16,
             Bt + (size_t)bh * 8704 + r * 64 + c * 8);
    }
    cp_commit();

    const uint32_t aoff = sb + (uint32_t)(w * 16 + (lane & 15)) * AT_ROWB +
                          (uint32_t)(lane >> 4) * 16;
    const uint32_t boff = sbB + (uint32_t)(((lane >> 4) << 3) + (lane & 7)) * AT_ROWB +
                          (uint32_t)((lane >> 3) & 1) * 16;

    for (int tt = 0; tt < 2; tt++) {
        const int lt = ltp * 2 + tt;
        for (int idx = tid; idx < 1024; idx += 256) {
            int r = idx >> 3, c = idx & 7;
            cp16(sb + (uint32_t)r * AT_ROWB + c * 16,
                 QKV + ((size_t)(b * 8192 + lt * 128 + r)) * D3_ + h * 64 + c * 8);
        }
        cp_commit();
        cp_wait<0>();
        __syncthreads();

        float acc[17][4];
        #pragma unroll
        for (int i = 0; i < 17; i++)
            #pragma unroll
            for (int q = 0; q < 4; q++) acc[i][q] = 0.0f;

        #pragma unroll
        for (int s = 0; s < 4; s++) {
            uint32_t a[4];
            ldsm4(a[0], a[1], a[2], a[3], aoff + s * 32);
            #pragma unroll
            for (int p = 0; p < 9; p++) {
                uint32_t bb[4];
                ldsm4(bb[0], bb[1], bb[2], bb[3], boff + (uint32_t)p * 16 * AT_ROWB + s * 32);
                mma16816(acc[2 * p], a, bb[0], bb[1]);
                if (p < 8) mma16816(acc[2 * p + 1], a, bb[2], bb[3]);
            }
        }

        float v0 = acc[16][0] + acc[16][1];
        float v1 = acc[16][2] + acc[16][3];
        float zd0 = __shfl_sync(0xffffffffu, v0, lane & 0x1C);
        float zd1 = __shfl_sync(0xffffffffu, v1, lane & 0x1C);
        float z0 = 1.0f / (zd0 + EPS_);
        float z1 = 1.0f / (zd1 + EPS_);

        size_t row0 = (size_t)(b * 8192 + lt * 128 + w * 16 + (lane >> 2));
        int colb = h * 64 + (lane & 3) * 2;
        #pragma unroll
        for (int nb = 0; nb < 8; nb++) {
            __half2 o0 = __floats2half2_rn((acc[nb][0] + acc[nb + 8][0]) * z0,
                                           (acc[nb][1] + acc[nb + 8][1]) * z0);
            __half2 o1 = __floats2half2_rn((acc[nb][2] + acc[nb + 8][2]) * z1,
                                           (acc[nb][3] + acc[nb + 8][3]) * z1);
            *reinterpret_cast<__half2*>(A2 + row0 * D_ + colb + nb * 8)       = o0;
            *reinterpret_cast<__half2*>(A2 + (row0 + 8) * D_ + colb + nb * 8) = o1;
        }
        __syncthreads();
    }
}

// ---------------------------------------------------------------------------
// Launch
// ---------------------------------------------------------------------------
extern "C" void kernel_launch(void* const* d_in, const int* in_sizes, int n_in,
                              void* d_out, int out_size) {
    const float* q     = (const float*)d_in[0];
    const float* k     = (const float*)d_in[1];
    const float* v     = (const float*)d_in[2];
    const float* w_qkv = (const float*)d_in[3];
    const float* w_out = (const float*)d_in[4];
    const float* b_out = (const float*)d_in[5];
    float* out = (float*)d_out;

    __half *A1, *W1, *A2, *W2, *QKV, *Bt;
    cudaGetSymbolAddress((void**)&A1,  g_A1);
    cudaGetSymbolAddress((void**)&W1,  g_W1);
    cudaGetSymbolAddress((void**)&A2,  g_A2);
    cudaGetSymbolAddress((void**)&W2,  g_W2);
    cudaGetSymbolAddress((void**)&QKV, g_QKV);
    cudaGetSymbolAddress((void**)&Bt,  g_Battn);

    cudaFuncSetAttribute(gemm_h, cudaFuncAttributeMaxDynamicSharedMemorySize, GSMEM);

    // 1) fp16 conversions
    conv1_k<<<98304, 256>>>((const float4*)q, (const float4*)k, (const float4*)v);
    convw_k<<<2304, 256>>>(w_qkv, W1);
    convw_k<<<256, 256>>>(w_out, W2);

    // 2) QKV(fp16) = elu-fused X @ W_qkv^T   (R13 best GEMM1)
    gemm_h<<<512 * 12, 256, GSMEM>>>(A1, W1, nullptr, QKV, nullptr, 1536, 12, 1536, 0);

    // 3) kv state (HMMA) -> reduce -> attention via HMMA (2 tiles/block)
    kv_mma<<<dim3(64, NSC), 256>>>(QKV);
    kv_reduce<<<1040, 256>>>();
    attn_mma<<<2048, 256>>>(QKV, Bt, A2);

    // 4) out = A2 @ W2^T + b_out
    gemm_h<<<512 * 4, 256, GSMEM>>>(A2, W2, out, nullptr, b_out, 512, 4, 512, 1);
}